// round 1
// baseline (speedup 1.0000x reference)
#include <cuda_runtime.h>
#include <math.h>

#define Tn 524288
#define Bn 4096
#define Hn 512
#define EPS 1e-5f

// Scratch (device globals: no allocation allowed in kernel_launch)
__device__ float d_bow[(size_t)Bn * Hn];   // 8 MB
__device__ float d_z[(size_t)Bn * Hn];     // 8 MB
__device__ float d_mu[Hn];
__device__ float d_invstd[Hn];

// ---------------------------------------------------------------------------
// lower_bound on sorted int array
// ---------------------------------------------------------------------------
__device__ __forceinline__ int lb(const int* __restrict__ a, int n, int key) {
    int lo = 0, hi = n;
    while (lo < hi) {
        int m = (lo + hi) >> 1;
        if (a[m] < key) lo = m + 1; else hi = m;
    }
    return lo;
}

// ---------------------------------------------------------------------------
// Kernel 1: embedding-bag (segment mean). One block per segment.
// 128 threads x float4 = 512 floats = one full emb row per token iteration.
// ---------------------------------------------------------------------------
__global__ __launch_bounds__(128)
void bag_kernel(const int* __restrict__ tokens,
                const int* __restrict__ seg,
                const float* __restrict__ emb) {
    int b = blockIdx.x;
    __shared__ int bounds[2];
    if (threadIdx.x < 2) bounds[threadIdx.x] = lb(seg, Tn, b + (int)threadIdx.x);
    __syncthreads();
    int start = bounds[0], end = bounds[1];

    int c = threadIdx.x;  // float4 index within row (0..127)
    float4 a0 = make_float4(0.f, 0.f, 0.f, 0.f);
    float4 a1 = make_float4(0.f, 0.f, 0.f, 0.f);
    float4 a2 = make_float4(0.f, 0.f, 0.f, 0.f);
    float4 a3 = make_float4(0.f, 0.f, 0.f, 0.f);

    int i = start;
    for (; i + 4 <= end; i += 4) {
        int t0 = tokens[i + 0];
        int t1 = tokens[i + 1];
        int t2 = tokens[i + 2];
        int t3 = tokens[i + 3];
        float4 v0 = ((const float4*)(emb + (size_t)t0 * Hn))[c];
        float4 v1 = ((const float4*)(emb + (size_t)t1 * Hn))[c];
        float4 v2 = ((const float4*)(emb + (size_t)t2 * Hn))[c];
        float4 v3 = ((const float4*)(emb + (size_t)t3 * Hn))[c];
        a0.x += v0.x; a0.y += v0.y; a0.z += v0.z; a0.w += v0.w;
        a1.x += v1.x; a1.y += v1.y; a1.z += v1.z; a1.w += v1.w;
        a2.x += v2.x; a2.y += v2.y; a2.z += v2.z; a2.w += v2.w;
        a3.x += v3.x; a3.y += v3.y; a3.z += v3.z; a3.w += v3.w;
    }
    for (; i < end; i++) {
        int t0 = tokens[i];
        float4 v0 = ((const float4*)(emb + (size_t)t0 * Hn))[c];
        a0.x += v0.x; a0.y += v0.y; a0.z += v0.z; a0.w += v0.w;
    }

    float inv = 1.0f / fmaxf((float)(end - start), 1.0f);
    float4 r;
    r.x = (a0.x + a1.x + a2.x + a3.x) * inv;
    r.y = (a0.y + a1.y + a2.y + a3.y) * inv;
    r.z = (a0.z + a1.z + a2.z + a3.z) * inv;
    r.w = (a0.w + a1.w + a2.w + a3.w) * inv;
    ((float4*)(d_bow + (size_t)b * Hn))[c] = r;
}

// ---------------------------------------------------------------------------
// Kernel 2: GEMM  z[i][j] = sum_k bow[i][k] * W1[j][k] + b1[j]
// BM=BN=128, BK=32, 256 threads, 8x8 microtile, transposed smem tiles.
// ---------------------------------------------------------------------------
#define BM 128
#define BN 128
#define BK 32
#define LDT (BM + 4)   // padded leading dim for transposed tiles (mult of 4 for float4)

__global__ __launch_bounds__(256)
void gemm_kernel(const float* __restrict__ W1, const float* __restrict__ b1) {
    __shared__ float As[BK][LDT];
    __shared__ float Bs[BK][LDT];

    int tid = threadIdx.x;
    int ty = tid >> 4;       // 0..15
    int tx = tid & 15;       // 0..15
    int rowBase = blockIdx.x * BM;
    int colBase = blockIdx.y * BN;

    float acc[8][8];
#pragma unroll
    for (int ii = 0; ii < 8; ii++)
#pragma unroll
        for (int jj = 0; jj < 8; jj++) acc[ii][jj] = 0.f;

    const float* A = d_bow;

    for (int k0 = 0; k0 < Hn; k0 += BK) {
#pragma unroll
        for (int l = 0; l < 4; l++) {
            int f = l * 256 + tid;       // float4 id 0..1023
            int r = f >> 3;              // row within tile 0..127
            int kq = f & 7;              // float4 within the 32 k-cols
            float4 va = *(const float4*)(A + (size_t)(rowBase + r) * Hn + k0 + kq * 4);
            As[kq * 4 + 0][r] = va.x;
            As[kq * 4 + 1][r] = va.y;
            As[kq * 4 + 2][r] = va.z;
            As[kq * 4 + 3][r] = va.w;
            float4 vb = *(const float4*)(W1 + (size_t)(colBase + r) * Hn + k0 + kq * 4);
            Bs[kq * 4 + 0][r] = vb.x;
            Bs[kq * 4 + 1][r] = vb.y;
            Bs[kq * 4 + 2][r] = vb.z;
            Bs[kq * 4 + 3][r] = vb.w;
        }
        __syncthreads();

#pragma unroll
        for (int kk = 0; kk < BK; kk++) {
            float a[8], bfr[8];
            *(float4*)(a)     = *(const float4*)&As[kk][ty * 8];
            *(float4*)(a + 4) = *(const float4*)&As[kk][ty * 8 + 4];
            *(float4*)(bfr)     = *(const float4*)&Bs[kk][tx * 8];
            *(float4*)(bfr + 4) = *(const float4*)&Bs[kk][tx * 8 + 4];
#pragma unroll
            for (int ii = 0; ii < 8; ii++)
#pragma unroll
                for (int jj = 0; jj < 8; jj++)
                    acc[ii][jj] += a[ii] * bfr[jj];
        }
        __syncthreads();
    }

    // epilogue: add bias, write z
    float bias[8];
    *(float4*)(bias)     = *(const float4*)(b1 + colBase + tx * 8);
    *(float4*)(bias + 4) = *(const float4*)(b1 + colBase + tx * 8 + 4);

#pragma unroll
    for (int ii = 0; ii < 8; ii++) {
        int row = rowBase + ty * 8 + ii;
        float* zr = d_z + (size_t)row * Hn + colBase + tx * 8;
        float4 o0, o1;
        o0.x = acc[ii][0] + bias[0];
        o0.y = acc[ii][1] + bias[1];
        o0.z = acc[ii][2] + bias[2];
        o0.w = acc[ii][3] + bias[3];
        o1.x = acc[ii][4] + bias[4];
        o1.y = acc[ii][5] + bias[5];
        o1.z = acc[ii][6] + bias[6];
        o1.w = acc[ii][7] + bias[7];
        *(float4*)(zr)     = o0;
        *(float4*)(zr + 4) = o1;
    }
}

// ---------------------------------------------------------------------------
// Kernel 3: per-column mean/invstd over B rows (deterministic).
// blockDim (32, 8); 16 blocks; each block owns 32 consecutive columns.
// ---------------------------------------------------------------------------
__global__ void stats_kernel() {
    int tx = threadIdx.x;           // 0..31 -> column within block
    int ty = threadIdx.y;           // 0..7  -> row stride phase
    int col = blockIdx.x * 32 + tx;

    float s = 0.f, sq = 0.f;
    for (int i = ty; i < Bn; i += 8) {
        float v = d_z[(size_t)i * Hn + col];
        s += v;
        sq += v * v;
    }
    __shared__ float ss[8][32];
    __shared__ float ssq[8][32];
    ss[ty][tx] = s;
    ssq[ty][tx] = sq;
    __syncthreads();
    if (ty == 0) {
#pragma unroll
        for (int y = 1; y < 8; y++) { s += ss[y][tx]; sq += ssq[y][tx]; }
        float mu = s * (1.0f / Bn);
        float var = sq * (1.0f / Bn) - mu * mu;
        d_mu[col] = mu;
        d_invstd[col] = rsqrtf(var + EPS);
    }
}

// ---------------------------------------------------------------------------
// Kernel 4: normalize + ReLU + dot(w2) -> logits. One warp per row.
// ---------------------------------------------------------------------------
__global__ __launch_bounds__(256)
void logits_kernel(const float* __restrict__ gamma,
                   const float* __restrict__ beta,
                   const float* __restrict__ w2,
                   const float* __restrict__ b2,
                   float* __restrict__ out) {
    int warp = threadIdx.x >> 5;
    int lane = threadIdx.x & 31;
    int row = blockIdx.x * 8 + warp;

    const float4* zr = (const float4*)(d_z + (size_t)row * Hn);
    float sum = 0.f;
#pragma unroll
    for (int q = 0; q < 4; q++) {
        int c4 = lane + 32 * q;
        float4 z  = zr[c4];
        float4 mu = ((const float4*)d_mu)[c4];
        float4 is = ((const float4*)d_invstd)[c4];
        float4 g  = ((const float4*)gamma)[c4];
        float4 be = ((const float4*)beta)[c4];
        float4 w  = ((const float4*)w2)[c4];
        sum += fmaxf((z.x - mu.x) * is.x * g.x + be.x, 0.f) * w.x;
        sum += fmaxf((z.y - mu.y) * is.y * g.y + be.y, 0.f) * w.y;
        sum += fmaxf((z.z - mu.z) * is.z * g.z + be.z, 0.f) * w.z;
        sum += fmaxf((z.w - mu.w) * is.w * g.w + be.w, 0.f) * w.w;
    }
#pragma unroll
    for (int o = 16; o > 0; o >>= 1) sum += __shfl_xor_sync(0xFFFFFFFFu, sum, o);
    if (lane == 0) out[1 + row] = sum + b2[0];
}

// ---------------------------------------------------------------------------
// Kernel 5: BCEWithLogits mean loss over logits (reads out[1..Bn]).
// ---------------------------------------------------------------------------
__global__ void loss_kernel(const float* __restrict__ t, float* __restrict__ out) {
    float acc = 0.f;
    for (int i = threadIdx.x; i < Bn; i += 1024) {
        float x = out[1 + i];
        float sp = fmaxf(x, 0.f) + log1pf(expf(-fabsf(x)));
        acc += sp - t[i] * x;
    }
    __shared__ float s[1024];
    s[threadIdx.x] = acc;
    __syncthreads();
    for (int st = 512; st > 0; st >>= 1) {
        if (threadIdx.x < st) s[threadIdx.x] += s[threadIdx.x + st];
        __syncthreads();
    }
    if (threadIdx.x == 0) out[0] = s[0] * (1.0f / Bn);
}

// ---------------------------------------------------------------------------
// launch
// ---------------------------------------------------------------------------
extern "C" void kernel_launch(void* const* d_in, const int* in_sizes, int n_in,
                              void* d_out, int out_size) {
    const int*   tokens = (const int*)d_in[0];
    const int*   seg    = (const int*)d_in[1];
    const float* t      = (const float*)d_in[2];
    const float* emb    = (const float*)d_in[3];
    const float* W1     = (const float*)d_in[4];
    const float* b1     = (const float*)d_in[5];
    const float* gamma  = (const float*)d_in[6];
    const float* beta   = (const float*)d_in[7];
    const float* w2     = (const float*)d_in[8];
    const float* b2     = (const float*)d_in[9];
    float* out = (float*)d_out;

    bag_kernel<<<Bn, 128>>>(tokens, seg, emb);
    gemm_kernel<<<dim3(Bn / BM, Hn / BN), 256>>>(W1, b1);
    stats_kernel<<<16, dim3(32, 8)>>>();
    logits_kernel<<<Bn / 8, 256>>>(gamma, beta, w2, b2, out);
    loss_kernel<<<1, 1024>>>(t, out);
}